// round 13
// baseline (speedup 1.0000x reference)
#include <cuda_runtime.h>
#include <cuda_bf16.h>
#include <math.h>

// Problem constants
#define FD      128
#define K       15
#define FS      160
#define OV      40
#define NF      500
#define BATCH   32
#define NTOT    (NF * FS)          // 80000 samples per batch row
#define NFR     (BATCH * NF)       // 16000 frames total

// C = ln(10)/20 ; LOG_GAIN_LIMIT = 10*C ; GAIN_A = 6*C ; GAIN_B = 0
#define LOG_GAIN_LIMIT 1.1512925464970229f
#define GAIN_A         0.6907755278982137f
#define PI_F           3.14159265358979323846f

// Per-frame coefficients: [0..14] = taps * gain / ||k|| (folded), [15] = ggain
__device__ __align__(16) float g_coef[NFR * 16];

// ---------------------------------------------------------------------------
// Kernel A (dots): unchanged from R12 (measured win).
// 256-thread blocks, 4 frames/warp, weights staged once per block with a
// (q,seg) swizzle so every weight LDS.128 is 1 conflict-free wavefront
// broadcast to 4 frames. 17 reg accumulators, 3 shuffle levels, in-thread
// epilogue, float4 coefficient stores.
// ---------------------------------------------------------------------------
__global__ __launch_bounds__(256)
void dots_kernel(const float* __restrict__ features,
                 const float* __restrict__ ck_w, const float* __restrict__ ck_b,
                 const float* __restrict__ fg_w, const float* __restrict__ fg_b,
                 const float* __restrict__ gg_w, const float* __restrict__ gg_b)
{
    __shared__ __align__(16) float s_w[17 * 128];        // 8.5 KB, swizzled
    const int tid  = threadIdx.x;
    const int lane = tid & 31;
    const int warp = tid >> 5;
    const int fr0  = blockIdx.x * 32 + warp * 4;         // grid = NFR/32 = 500
    const int j    = lane >> 3;                          // frame within warp
    const int seg  = lane & 7;                           // feature segment
    const int fr   = fr0 + j;

    // stage weights with swizzle: rows 0..14 = ck_w, 15 = fg_w, 16 = gg_w
    for (int o4 = tid; o4 < 544; o4 += 256) {
        const int r  = o4 >> 5;          // row 0..16
        const int c4 = o4 & 31;          // float4 column within row
        float4 v;
        if (r < 15)       v = __ldg((const float4*)ck_w + r * 32 + c4);
        else if (r == 15) v = __ldg((const float4*)fg_w + c4);
        else              v = __ldg((const float4*)gg_w + c4);
        const int dst4 = r * 32 + (c4 & 3) * 8 + (c4 >> 2);
        *(float4*)(s_w + dst4 * 4) = v;
    }
    __syncthreads();

    const float4* fp = (const float4*)(features + (size_t)fr * FD) + seg * 4;
    const float4 f0 = __ldg(fp + 0), f1 = __ldg(fp + 1),
                 f2 = __ldg(fp + 2), f3 = __ldg(fp + 3);

    float acc[17];
    #pragma unroll
    for (int r = 0; r < 17; r++) {
        const float4* wr = (const float4*)(s_w + r * 128) + seg;
        const float4 w0 = wr[0], w1 = wr[8], w2 = wr[16], w3 = wr[24];
        acc[r]  = f0.x*w0.x + f0.y*w0.y + f0.z*w0.z + f0.w*w0.w;
        acc[r] += f1.x*w1.x + f1.y*w1.y + f1.z*w1.z + f1.w*w1.w;
        acc[r] += f2.x*w2.x + f2.y*w2.y + f2.z*w2.z + f2.w*w2.w;
        acc[r] += f3.x*w3.x + f3.y*w3.y + f3.z*w3.z + f3.w*w3.w;
    }

    #pragma unroll
    for (int r = 0; r < 17; r++) {
        acc[r] += __shfl_xor_sync(0xffffffffu, acc[r], 1);
        acc[r] += __shfl_xor_sync(0xffffffffu, acc[r], 2);
        acc[r] += __shfl_xor_sync(0xffffffffu, acc[r], 4);
    }

    if (seg == 0) {
        float d[15], ss = 0.f;
        #pragma unroll
        for (int r = 0; r < 15; r++) {
            d[r] = acc[r] + __ldg(ck_b + r);
            ss += d[r] * d[r];
        }
        const float fgd = acc[15] + __ldg(fg_b);
        const float ggd = acc[16] + __ldg(gg_b);
        const float gs  = __expf(LOG_GAIN_LIMIT - fmaxf(fgd, 0.f))
                        / (1e-6f + sqrtf(ss));
        const float gg  = __expf(GAIN_A * tanhf(ggd));
        float4* dst = (float4*)(g_coef + (size_t)fr * 16);
        dst[0] = make_float4(d[0]*gs,  d[1]*gs,  d[2]*gs,  d[3]*gs);
        dst[1] = make_float4(d[4]*gs,  d[5]*gs,  d[6]*gs,  d[7]*gs);
        dst[2] = make_float4(d[8]*gs,  d[9]*gs,  d[10]*gs, d[11]*gs);
        dst[3] = make_float4(d[12]*gs, d[13]*gs, d[14]*gs, gg);
    }
}

// ---------------------------------------------------------------------------
// Kernel B (fir): R8 structure with ONE change — the prev-frame tail
// recompute is distributed over lanes 0..19 (2 outputs each, shared 16-float
// window) instead of 5 outputs on lanes 0..7. Tails + window coefs are
// bounced through the dead xc region of shared ([0..80)).
// Shared per warp (420 floats):
//   [  0..174)  xc (later reused: [0..40) tails, [40..80) w2, then output)
//   [174..228)  xp : lag-gathered window, prev-frame tail
//   [228..388)  pt : pass-through x[f*FS .. +160)
//   [388..404)  coefs current frame (15 taps + gg)
//   [404..420)  coefs previous frame (15 taps + gg)
// ---------------------------------------------------------------------------
__global__ __launch_bounds__(256)
void fir_kernel(const float* __restrict__ x,
                const int*   __restrict__ lags,
                float*       __restrict__ out)
{
    __shared__ float sh[8][420];
    const int lane = threadIdx.x & 31;
    const int warp = threadIdx.x >> 5;
    const int fr   = blockIdx.x * 8 + warp;     // grid = NFR/8 exactly
    const int b    = fr / NF;
    const int f    = fr % NF;

    const float* xb = x + (size_t)b * NTOT;
    float* s = sh[warp];
    const int base = f * FS - 7;                // f*FS - PAD_L
    const int lag  = __ldg(lags + fr);

    // stage x windows (coalesced within the warp) — identical to R8
    #pragma unroll
    for (int t = lane; t < 174; t += 32) {
        const int idx = base - lag + t;
        s[t] = (idx >= 0 && idx < NTOT) ? __ldg(xb + idx) : 0.f;
    }
    if (f > 0) {
        const int lagp = __ldg(lags + fr - 1);
        #pragma unroll
        for (int t = lane; t < 54; t += 32) {
            const int idx = base - lagp + t;
            s[174 + t] = (idx >= 0) ? __ldg(xb + idx) : 0.f;
        }
    }
    #pragma unroll
    for (int t = lane; t < FS; t += 32)
        s[228 + t] = __ldg(xb + f * FS + t);

    if (lane < 16)       s[388 + lane]        = g_coef[fr * 16 + lane];
    else if (f > 0)      s[404 + (lane - 16)] = g_coef[(fr - 1) * 16 + (lane - 16)];
    __syncwarp();

    float tap[15];
    #pragma unroll
    for (int k = 0; k < 15; k++) tap[k] = s[388 + k];
    const float gg = s[403];

    float xv[19];
    #pragma unroll
    for (int j = 0; j < 19; j++) xv[j] = s[5 * lane + j];

    float res[5];
    #pragma unroll
    for (int i = 0; i < 5; i++) {
        float conv = 0.f;
        #pragma unroll
        for (int k = 0; k < 15; k++)
            conv = fmaf(xv[i + k], tap[k], conv);
        res[i] = gg * (conv + s[228 + 5 * lane + i]);
    }

    // ---- distributed tail recompute: lanes 0..19, outputs o=2*lane, 2*lane+1
    float t0 = 0.f, t1 = 0.f, w20 = 0.f, w21 = 0.f;
    if (lane < 20) {
        const int o = 2 * lane;
        w20 = 0.5f + 0.5f * __cosf((o + 0.5f) * (PI_F / OV));
        w21 = 0.5f + 0.5f * __cosf((o + 1.5f) * (PI_F / OV));
        if (f > 0) {
            float tp[15];
            #pragma unroll
            for (int k = 0; k < 15; k++) tp[k] = s[404 + k];
            const float ggp = s[419];
            float xw[16];
            #pragma unroll
            for (int j = 0; j < 16; j++) xw[j] = s[174 + o + j];
            float c0 = 0.f, c1 = 0.f;
            #pragma unroll
            for (int k = 0; k < 15; k++) {
                c0 = fmaf(xw[k],     tp[k], c0);
                c1 = fmaf(xw[k + 1], tp[k], c1);
            }
            // prev frame's pass-through at l=FS+o equals x[f*FS + o] = pt[o]
            t0 = ggp * (c0 + s[228 + o]);
            t1 = ggp * (c1 + s[228 + o + 1]);
        }
    }
    __syncwarp();                 // all xv reads done before reusing xc region
    if (lane < 20) {
        s[2 * lane]          = t0;
        s[2 * lane + 1]      = t1;
        s[40 + 2 * lane]     = w20;
        s[40 + 2 * lane + 1] = w21;
    }
    __syncwarp();

    // head blend (o < 40): lanes 0..7 own those outputs
    if (lane < 8) {
        #pragma unroll
        for (int i = 0; i < 5; i++) {
            const int j5 = 5 * lane + i;
            const float w2 = s[40 + j5];
            res[i] = res[i] * (1.f - w2) + s[j5] * w2;   // win1 = 1 - win2
        }
    }

    // bounce through shared for coalesced stores
    __syncwarp();
    #pragma unroll
    for (int i = 0; i < 5; i++) s[5 * lane + i] = res[i];
    __syncwarp();

    float* op = out + (size_t)b * NTOT + f * FS;
    #pragma unroll
    for (int i = 0; i < 5; i++)
        op[lane + 32 * i] = s[lane + 32 * i];
}

extern "C" void kernel_launch(void* const* d_in, const int* in_sizes, int n_in,
                              void* d_out, int out_size)
{
    const float* x        = (const float*)d_in[0];
    const float* features = (const float*)d_in[1];
    const int*   lags     = (const int*)  d_in[2];
    const float* ck_w     = (const float*)d_in[3];
    const float* ck_b     = (const float*)d_in[4];
    const float* fg_w     = (const float*)d_in[5];
    const float* fg_b     = (const float*)d_in[6];
    const float* gg_w     = (const float*)d_in[7];
    const float* gg_b     = (const float*)d_in[8];

    dots_kernel<<<NFR / 32, 256>>>(features, ck_w, ck_b, fg_w, fg_b, gg_w, gg_b);
    fir_kernel<<<NFR / 8, 256>>>(x, lags, (float*)d_out);
}